// round 5
// baseline (speedup 1.0000x reference)
#include <cuda_runtime.h>
#include <cstdint>

// ---------------------------------------------------------------------------
// f = -d( sum(mlp(pos)) )/dpos for a 2->8->4->2 ReLU MLP.
// The gradient is piecewise constant in the ReLU masks (m1: 8 bits, m2: 4 bits):
//   force(m1,m2) = -sum_{k: m1_k active} v[m2][k] * W1[k,:]
//   v[m2][k]     =  sum_{j: m2_j active} g3_j * W2[j][k],  g3_j = W3[0][j]+W3[1][j]
// Split the 12-bit LUT into two 8-bit tables (low/high halves of m1):
//   force = A[m2*16 + m1_lo4] + B[m2*16 + m1_hi4]      (negation folded in)
// Tables: 2 x 256 float2 = 4KB smem, built in ~80 ops/thread once per block.
// Inner loop per position: 24 fwd-L1 + 32 fwd-L2 + 16 mask-pack + 2 LDS.64
// + 2 FADD ~= 80 slots (vs ~110 before).
// ---------------------------------------------------------------------------

__device__ __forceinline__ unsigned prmt_(unsigned a, unsigned b, unsigned sel) {
    unsigned d;
    asm("prmt.b32 %0, %1, %2, %3;" : "=r"(d) : "r"(a), "r"(b), "r"(sel));
    return d;
}
__device__ __forceinline__ int dp4a_(unsigned a, unsigned b, int c) {
    int d;
    asm("dp4a.u32.u32 %0, %1, %2, %3;" : "=r"(d) : "r"(a), "r"(b), "r"(c));
    return d;
}

struct Wts {
    float w1x[8], w1y[8], bb1[8];   // W1[k][0], W1[k][1], b1[k]
    float w2[4][8];                  // W2[j][k]
    float bb2[4];                    // b2[j]
};

__device__ __forceinline__ float2 force_one(float x, float y, const Wts& W,
                                            const float2* __restrict__ Atab,
                                            const float2* __restrict__ Btab) {
    // ---- forward layer 1 (same op order as round-1 -> identical masks) ----
    float h1p[8], h1[8];
#pragma unroll
    for (int k = 0; k < 8; k++) {
        h1p[k] = fmaf(x, W.w1x[k], fmaf(y, W.w1y[k], W.bb1[k]));
        h1[k]  = fmaxf(h1p[k], 0.0f);
    }
    // ---- forward layer 2 (signs only) ----
    float h2p[4];
#pragma unroll
    for (int j = 0; j < 4; j++) {
        float s = W.bb2[j];
#pragma unroll
        for (int k = 0; k < 8; k++) s = fmaf(h1[k], W.w2[j][k], s);
        h2p[j] = s;
    }
    // ---- pack sign bits: bit=1 iff value < 0 (inactive) ----
    unsigned a01 = prmt_(__float_as_uint(h1p[0]), __float_as_uint(h1p[1]), 0x00FBu);
    unsigned a23 = prmt_(__float_as_uint(h1p[2]), __float_as_uint(h1p[3]), 0x00FBu);
    unsigned a45 = prmt_(__float_as_uint(h1p[4]), __float_as_uint(h1p[5]), 0x00FBu);
    unsigned a67 = prmt_(__float_as_uint(h1p[6]), __float_as_uint(h1p[7]), 0x00FBu);
    unsigned aLo = prmt_(a01, a23, 0x5410u) & 0x01010101u;   // signs h1p[0..3]
    unsigned aHi = prmt_(a45, a67, 0x5410u) & 0x01010101u;   // signs h1p[4..7]

    unsigned b01 = prmt_(__float_as_uint(h2p[0]), __float_as_uint(h2p[1]), 0x00FBu);
    unsigned b23 = prmt_(__float_as_uint(h2p[2]), __float_as_uint(h2p[3]), 0x00FBu);
    unsigned bm  = prmt_(b01, b23, 0x5410u) & 0x01010101u;   // signs h2p[0..3]

    int base = dp4a_(bm, 0x08040201u, 0) << 4;               // m2 * 16
    int iA   = dp4a_(aLo, 0x08040201u, base);                // + m1_lo4
    int iB   = dp4a_(aHi, 0x08040201u, base);                // + m1_hi4

    float2 A = Atab[iA];
    float2 B = Btab[iB];
    return make_float2(A.x + B.x, A.y + B.y);                // already negated
}

__global__ __launch_bounds__(256, 3)
void toy_force_kernel(const float4* __restrict__ pos4,
                      const float* __restrict__ W1,
                      const float* __restrict__ b1,
                      const float* __restrict__ W2,
                      const float* __restrict__ b2,
                      const float* __restrict__ W3,
                      float4* __restrict__ out4,
                      int n4) {
    __shared__ float2 Atab[256];   // [m2*16 + m1_lo4]
    __shared__ float2 Btab[256];   // [m2*16 + m1_hi4]

    int t = threadIdx.x;

    // Load all weights into registers (uniform -> broadcast hits).
    Wts W;
#pragma unroll
    for (int k = 0; k < 8; k++) {
        W.w1x[k] = W1[k * 2 + 0];
        W.w1y[k] = W1[k * 2 + 1];
        W.bb1[k] = b1[k];
    }
#pragma unroll
    for (int j = 0; j < 4; j++) {
        W.bb2[j] = b2[j];
#pragma unroll
        for (int k = 0; k < 8; k++) W.w2[j][k] = W2[j * 8 + k];
    }
    float g3[4];
#pragma unroll
    for (int j = 0; j < 4; j++) g3[j] = W3[j] + W3[4 + j];

    // Build A/B tables: thread t owns entry t of each table.
    {
        int m2  = t >> 4;        // layer-2 mask (bit=1 -> inactive)
        int sub = t & 15;        // 4 bits of m1 (low half for A, high half for B)
        float ax = 0.f, ay = 0.f, bx = 0.f, by = 0.f;
#pragma unroll
        for (int k = 0; k < 4; k++) {
            if (!((sub >> k) & 1)) {     // m1 bit clear -> neuron active
                float vA = 0.f, vB = 0.f;
#pragma unroll
                for (int j = 0; j < 4; j++) {
                    if (!((m2 >> j) & 1)) {
                        vA += g3[j] * W.w2[j][k];
                        vB += g3[j] * W.w2[j][k + 4];
                    }
                }
                ax = fmaf(vA, W.w1x[k], ax);
                ay = fmaf(vA, W.w1y[k], ay);
                bx = fmaf(vB, W.w1x[k + 4], bx);
                by = fmaf(vB, W.w1y[k + 4], by);
            }
        }
        Atab[t] = make_float2(-ax, -ay);  // fold the final negation in
        Btab[t] = make_float2(-bx, -by);
    }
    __syncthreads();

    // 2 float4 per thread, loads front-batched (MLP=2), coalesced per batch.
    int base = blockIdx.x * (256 * 2) + t;
    int i0 = base, i1 = base + 256;

    float4 p0, p1;
    bool v0 = (i0 < n4), v1 = (i1 < n4);
    if (v0) p0 = pos4[i0];
    if (v1) p1 = pos4[i1];

    if (v0) {
        float2 f0 = force_one(p0.x, p0.y, W, Atab, Btab);
        float2 f1 = force_one(p0.z, p0.w, W, Atab, Btab);
        out4[i0] = make_float4(f0.x, f0.y, f1.x, f1.y);
    }
    if (v1) {
        float2 f0 = force_one(p1.x, p1.y, W, Atab, Btab);
        float2 f1 = force_one(p1.z, p1.w, W, Atab, Btab);
        out4[i1] = make_float4(f0.x, f0.y, f1.x, f1.y);
    }
}

extern "C" void kernel_launch(void* const* d_in, const int* in_sizes, int n_in,
                              void* d_out, int out_size) {
    const float* pos = (const float*)d_in[0];   // [N,2] float32
    const float* W1  = (const float*)d_in[1];   // [8,2]
    const float* b1  = (const float*)d_in[2];   // [8]
    const float* W2  = (const float*)d_in[3];   // [4,8]
    const float* b2  = (const float*)d_in[4];   // [4]
    const float* W3  = (const float*)d_in[5];   // [2,4]
    float* out = (float*)d_out;                 // [N,2] float32

    int n4 = in_sizes[0] / 4;                   // float4s (2 positions each)
    const int threads = 256;
    const int per_block = threads * 2;          // 2 float4 per thread
    int blocks = (n4 + per_block - 1) / per_block;

    toy_force_kernel<<<blocks, threads>>>(
        (const float4*)pos, W1, b1, W2, b2, W3, (float4*)out, n4);
}